// round 1
// baseline (speedup 1.0000x reference)
#include <cuda_runtime.h>
#include <cstdint>

// ---------------------------------------------------------------------------
// HybridBlock: RMS -> {k,v,r} GEMMs -> RWKV chunked scan -> o-GEMM(+res)
//              -> RMS -> fc-GEMM(leaky^2) -> mlp-GEMM(+res)
// Precision: tf32 mma.sync for all GEMMs, fp32 everywhere else.
// ---------------------------------------------------------------------------

#define S_LEN 4096
#define B_SZ  4
#define D_DIM 1024
#define H_DIM 4096
#define M_ROWS (B_SZ * S_LEN)      // 16384
#define CH_L  128                  // scan chunk length
#define CH_C  (S_LEN / CH_L)       // 32 chunks

// Scratch (device globals: allocation-free per harness rules)
__device__ float g_normed[(size_t)M_ROWS * D_DIM];
__device__ float g_k[(size_t)M_ROWS * D_DIM];
__device__ float g_v[(size_t)M_ROWS * D_DIM];
__device__ float g_r[(size_t)M_ROWS * D_DIM];
__device__ float g_a[(size_t)M_ROWS * D_DIM];     // r * wkv  (A for o-GEMM)
__device__ float g_x1[(size_t)M_ROWS * D_DIM];    // x + mixer residual
__device__ float g_h2[(size_t)M_ROWS * H_DIM];    // leaky(h)^2
__device__ float g_carry[CH_C * B_SZ * D_DIM];
__device__ float g_entry[CH_C * B_SZ * D_DIM];

// ---------------------------------------------------------------------------
// RMS norm: one block per row (D=1024, 256 threads, 1 float4/thread)
// ---------------------------------------------------------------------------
__global__ void rms_kernel(const float* __restrict__ x, float* __restrict__ out) {
    const int row = blockIdx.x;
    const float4 va = reinterpret_cast<const float4*>(x + (size_t)row * D_DIM)[threadIdx.x];
    float ss = va.x * va.x + va.y * va.y + va.z * va.z + va.w * va.w;
    #pragma unroll
    for (int o = 16; o > 0; o >>= 1) ss += __shfl_xor_sync(0xffffffffu, ss, o);

    __shared__ float wsum[8];
    const int wid = threadIdx.x >> 5, lid = threadIdx.x & 31;
    if (lid == 0) wsum[wid] = ss;
    __syncthreads();
    if (wid == 0) {
        float t = (lid < 8) ? wsum[lid] : 0.f;
        #pragma unroll
        for (int o = 4; o > 0; o >>= 1) t += __shfl_xor_sync(0xffffffffu, t, o);
        if (lid == 0) wsum[0] = t;
    }
    __syncthreads();
    const float inv = rsqrtf(wsum[0] * (1.0f / (float)D_DIM) + 1e-6f);
    float4 o4;
    o4.x = va.x * inv; o4.y = va.y * inv; o4.z = va.z * inv; o4.w = va.w * inv;
    reinterpret_cast<float4*>(out + (size_t)row * D_DIM)[threadIdx.x] = o4;
}

// ---------------------------------------------------------------------------
// RWKV chunked scan.
// step: wkv_t = s_{t-1} + eu*kv_t ;  s_t = ew*s_{t-1} + kv_t ;  s_0 = 0
// ew = exp(-exp(td)), eu = exp(tf). Per-channel constant decay => exact
// chunk factorization: s_end = ew^L * s_start + sum_i ew^{L-1-i} kv_i.
// ---------------------------------------------------------------------------
__global__ void scan_carry(const float* __restrict__ k, const float* __restrict__ v,
                           const float* __restrict__ td) {
    const int d = blockIdx.x * 256 + threadIdx.x;
    const int c = blockIdx.y, b = blockIdx.z;
    const float ew = expf(-expf(td[d]));
    size_t base = ((size_t)b * S_LEN + (size_t)c * CH_L) * D_DIM + d;
    float carry = 0.f;
    #pragma unroll 4
    for (int i = 0; i < CH_L; i++) {
        const float kv = k[base] * v[base];
        carry = ew * carry + kv;
        base += D_DIM;
    }
    g_carry[((size_t)c * B_SZ + b) * D_DIM + d] = carry;
}

__global__ void scan_combine(const float* __restrict__ td) {
    const int d = blockIdx.x * 256 + threadIdx.x;
    const int b = blockIdx.y;
    const float ewL = expf(-(float)CH_L * expf(td[d]));  // ew^L exactly
    float s = 0.f;
    #pragma unroll
    for (int c = 0; c < CH_C; c++) {
        const size_t idx = ((size_t)c * B_SZ + b) * D_DIM + d;
        g_entry[idx] = s;
        s = ewL * s + g_carry[idx];
    }
}

__global__ void scan_apply(const float* __restrict__ k, const float* __restrict__ v,
                           const float* __restrict__ r,
                           const float* __restrict__ td, const float* __restrict__ tfirst) {
    const int d = blockIdx.x * 256 + threadIdx.x;
    const int c = blockIdx.y, b = blockIdx.z;
    const float ew = expf(-expf(td[d]));
    const float eu = expf(tfirst[d]);
    float s = g_entry[((size_t)c * B_SZ + b) * D_DIM + d];
    size_t base = ((size_t)b * S_LEN + (size_t)c * CH_L) * D_DIM + d;
    #pragma unroll 4
    for (int i = 0; i < CH_L; i++) {
        const float kv = k[base] * v[base];
        const float wkv = s + eu * kv;
        g_a[base] = r[base] * wkv;
        s = ew * s + kv;
        base += D_DIM;
    }
}

// ---------------------------------------------------------------------------
// tf32 GEMM: C[M,N] = A[M,K] @ B[N,K]^T   (both K-major)
// Block 128x128x16, 256 threads, 8 warps (2x4), warp tile 64x32,
// mma.sync.m16n8k8 tf32, double-buffered smem, register-staged loads.
// EPI: 0=none 1=sigmoid 2=res+scale*acc 3=(leaky0.5)^2
// ---------------------------------------------------------------------------
#define BMT 128
#define BNT 128
#define BKT 16
#define BSTR 20   // +4 floats pad: conflict-free, keeps 16B alignment

__device__ __forceinline__ uint32_t f2tf32(float f) {
    uint32_t u;
    asm("cvt.rna.tf32.f32 %0, %1;" : "=r"(u) : "f"(f));
    return u;
}

template <int EPI>
__device__ __forceinline__ void epi_store(float* __restrict__ C,
                                          const float* __restrict__ res,
                                          const float* __restrict__ scale,
                                          int N, int r, int c, float v0, float v1) {
    if (EPI == 1) {
        v0 = 1.f / (1.f + expf(-v0));
        v1 = 1.f / (1.f + expf(-v1));
    } else if (EPI == 2) {
        const float2 rr = *reinterpret_cast<const float2*>(res + (size_t)r * N + c);
        v0 = rr.x + scale[c] * v0;
        v1 = rr.y + scale[c + 1] * v1;
    } else if (EPI == 3) {
        const float t0 = v0 > 0.f ? v0 : 0.5f * v0;
        const float t1 = v1 > 0.f ? v1 : 0.5f * v1;
        v0 = t0 * t0;
        v1 = t1 * t1;
    }
    *reinterpret_cast<float2*>(C + (size_t)r * N + c) = make_float2(v0, v1);
}

template <int EPI>
__global__ void __launch_bounds__(256, 1) gemm_tf32(
    const float* __restrict__ A, const float* __restrict__ Bw,
    float* __restrict__ C, int K, int N,
    const float* __restrict__ res, const float* __restrict__ scale)
{
    __shared__ alignas(16) uint32_t As[2][BMT * BSTR];
    __shared__ alignas(16) uint32_t Bs[2][BNT * BSTR];

    const int tid  = threadIdx.x;
    const int bn   = blockIdx.x, bm = blockIdx.y;
    const int warp = tid >> 5, lane = tid & 31;
    const int wm = warp >> 2, wn = warp & 3;            // warps 2x4
    const int gid = lane >> 2, tig = lane & 3;          // mma group / in-group
    const int ldrow = tid >> 2;                         // 0..63
    const int ldc4  = (tid & 3) * 4;                    // 0,4,8,12

    const float* Ab = A  + (size_t)bm * BMT * K;
    const float* Bb = Bw + (size_t)bn * BNT * K;

    float acc[4][4][4];
    #pragma unroll
    for (int i = 0; i < 4; i++)
        #pragma unroll
        for (int j = 0; j < 4; j++)
            #pragma unroll
            for (int l = 0; l < 4; l++) acc[i][j][l] = 0.f;

    uint32_t ra[2][4], rb[2][4];
    const int KT = K / BKT;

    // prologue: fetch tile 0 -> regs -> smem[0]
    #pragma unroll
    for (int it = 0; it < 2; it++) {
        const int row = ldrow + it * 64;
        const float4 av = *reinterpret_cast<const float4*>(Ab + (size_t)row * K + ldc4);
        const float4 bv = *reinterpret_cast<const float4*>(Bb + (size_t)row * K + ldc4);
        ra[it][0] = f2tf32(av.x); ra[it][1] = f2tf32(av.y);
        ra[it][2] = f2tf32(av.z); ra[it][3] = f2tf32(av.w);
        rb[it][0] = f2tf32(bv.x); rb[it][1] = f2tf32(bv.y);
        rb[it][2] = f2tf32(bv.z); rb[it][3] = f2tf32(bv.w);
    }
    #pragma unroll
    for (int it = 0; it < 2; it++) {
        const int row = ldrow + it * 64;
        *reinterpret_cast<uint4*>(&As[0][row * BSTR + ldc4]) =
            make_uint4(ra[it][0], ra[it][1], ra[it][2], ra[it][3]);
        *reinterpret_cast<uint4*>(&Bs[0][row * BSTR + ldc4]) =
            make_uint4(rb[it][0], rb[it][1], rb[it][2], rb[it][3]);
    }
    __syncthreads();

    for (int kt = 0; kt < KT; kt++) {
        const int cur = kt & 1;

        if (kt + 1 < KT) {  // prefetch next tile into registers
            const int koff = (kt + 1) * BKT;
            #pragma unroll
            for (int it = 0; it < 2; it++) {
                const int row = ldrow + it * 64;
                const float4 av = *reinterpret_cast<const float4*>(Ab + (size_t)row * K + koff + ldc4);
                const float4 bv = *reinterpret_cast<const float4*>(Bb + (size_t)row * K + koff + ldc4);
                ra[it][0] = f2tf32(av.x); ra[it][1] = f2tf32(av.y);
                ra[it][2] = f2tf32(av.z); ra[it][3] = f2tf32(av.w);
                rb[it][0] = f2tf32(bv.x); rb[it][1] = f2tf32(bv.y);
                rb[it][2] = f2tf32(bv.z); rb[it][3] = f2tf32(bv.w);
            }
        }

        #pragma unroll
        for (int ks = 0; ks < 2; ks++) {
            const int k0 = ks * 8;
            uint32_t af[4][4], bf[4][2];
            #pragma unroll
            for (int mi = 0; mi < 4; mi++) {
                const int r0 = (wm * 64 + mi * 16 + gid) * BSTR + k0 + tig;
                af[mi][0] = As[cur][r0];
                af[mi][1] = As[cur][r0 + 8 * BSTR];
                af[mi][2] = As[cur][r0 + 4];
                af[mi][3] = As[cur][r0 + 8 * BSTR + 4];
            }
            #pragma unroll
            for (int ni = 0; ni < 4; ni++) {
                const int c0 = (wn * 32 + ni * 8 + gid) * BSTR + k0 + tig;
                bf[ni][0] = Bs[cur][c0];
                bf[ni][1] = Bs[cur][c0 + 4];
            }
            #pragma unroll
            for (int mi = 0; mi < 4; mi++)
                #pragma unroll
                for (int ni = 0; ni < 4; ni++) {
                    asm volatile(
                        "mma.sync.aligned.m16n8k8.row.col.f32.tf32.tf32.f32 "
                        "{%0,%1,%2,%3}, {%4,%5,%6,%7}, {%8,%9}, {%0,%1,%2,%3};\n"
                        : "+f"(acc[mi][ni][0]), "+f"(acc[mi][ni][1]),
                          "+f"(acc[mi][ni][2]), "+f"(acc[mi][ni][3])
                        : "r"(af[mi][0]), "r"(af[mi][1]), "r"(af[mi][2]), "r"(af[mi][3]),
                          "r"(bf[ni][0]), "r"(bf[ni][1]));
                }
        }

        if (kt + 1 < KT) {  // commit prefetched tile to the other buffer
            const int nxt = cur ^ 1;
            #pragma unroll
            for (int it = 0; it < 2; it++) {
                const int row = ldrow + it * 64;
                *reinterpret_cast<uint4*>(&As[nxt][row * BSTR + ldc4]) =
                    make_uint4(ra[it][0], ra[it][1], ra[it][2], ra[it][3]);
                *reinterpret_cast<uint4*>(&Bs[nxt][row * BSTR + ldc4]) =
                    make_uint4(rb[it][0], rb[it][1], rb[it][2], rb[it][3]);
            }
        }
        __syncthreads();
    }

    // epilogue
    const int row0 = bm * BMT + wm * 64 + gid;
    const int col0 = bn * BNT + wn * 32 + 2 * tig;
    #pragma unroll
    for (int mi = 0; mi < 4; mi++) {
        #pragma unroll
        for (int ni = 0; ni < 4; ni++) {
            const int gr = row0 + mi * 16;
            const int gc = col0 + ni * 8;
            epi_store<EPI>(C, res, scale, N, gr,     gc, acc[mi][ni][0], acc[mi][ni][1]);
            epi_store<EPI>(C, res, scale, N, gr + 8, gc, acc[mi][ni][2], acc[mi][ni][3]);
        }
    }
}

// ---------------------------------------------------------------------------
// Launch
// ---------------------------------------------------------------------------
extern "C" void kernel_launch(void* const* d_in, const int* in_sizes, int n_in,
                              void* d_out, int out_size) {
    const float* x     = (const float*)d_in[0];
    const float* Wk    = (const float*)d_in[1];
    const float* Wv    = (const float*)d_in[2];
    const float* Wr    = (const float*)d_in[3];
    const float* Wo    = (const float*)d_in[4];
    const float* td    = (const float*)d_in[5];
    const float* tfst  = (const float*)d_in[6];
    const float* mscl  = (const float*)d_in[7];
    const float* Wfc   = (const float*)d_in[8];
    const float* Wmlp  = (const float*)d_in[9];
    const float* pscl  = (const float*)d_in[10];
    float* out = (float*)d_out;

    float *p_normed, *p_k, *p_v, *p_r, *p_a, *p_x1, *p_h2;
    cudaGetSymbolAddress((void**)&p_normed, g_normed);
    cudaGetSymbolAddress((void**)&p_k, g_k);
    cudaGetSymbolAddress((void**)&p_v, g_v);
    cudaGetSymbolAddress((void**)&p_r, g_r);
    cudaGetSymbolAddress((void**)&p_a, g_a);
    cudaGetSymbolAddress((void**)&p_x1, g_x1);
    cudaGetSymbolAddress((void**)&p_h2, g_h2);

    const dim3 gemmD(D_DIM / BNT, M_ROWS / BMT);   // (8, 128)
    const dim3 gemmH(H_DIM / BNT, M_ROWS / BMT);   // (32, 128)

    // 1) RMS(x)
    rms_kernel<<<M_ROWS, 256>>>(x, p_normed);
    // 2) k, v, r
    gemm_tf32<0><<<gemmD, 256>>>(p_normed, Wk, p_k, D_DIM, D_DIM, nullptr, nullptr);
    gemm_tf32<0><<<gemmD, 256>>>(p_normed, Wv, p_v, D_DIM, D_DIM, nullptr, nullptr);
    gemm_tf32<1><<<gemmD, 256>>>(p_normed, Wr, p_r, D_DIM, D_DIM, nullptr, nullptr);
    // 3) chunked RWKV scan, fuse r*wkv into g_a
    scan_carry<<<dim3(D_DIM / 256, CH_C, B_SZ), 256>>>(p_k, p_v, td);
    scan_combine<<<dim3(D_DIM / 256, B_SZ), 256>>>(td);
    scan_apply<<<dim3(D_DIM / 256, CH_C, B_SZ), 256>>>(p_k, p_v, p_r, td, tfst);
    // 4) o-GEMM + residual -> x1
    gemm_tf32<2><<<gemmD, 256>>>(p_a, Wo, p_x1, D_DIM, D_DIM, x, mscl);
    // 5) RMS(x1)
    rms_kernel<<<M_ROWS, 256>>>(p_x1, p_normed);
    // 6) fc-GEMM with leaky(0.5)^2 epilogue -> h2
    gemm_tf32<3><<<gemmH, 256>>>(p_normed, Wfc, p_h2, D_DIM, H_DIM, nullptr, nullptr);
    // 7) mlp-GEMM + residual -> out
    gemm_tf32<2><<<gemmD, 256>>>(p_h2, Wmlp, out, H_DIM, D_DIM, p_x1, pscl);
}

// round 3
// speedup vs baseline: 2.2707x; 2.2707x over previous
#include <cuda_runtime.h>
#include <cstdint>

// ---------------------------------------------------------------------------
// HybridBlock: RMS -> {k,v,r} GEMMs -> RWKV chunked scan -> o-GEMM(+res)
//              -> RMS -> fc-GEMM(leaky^2) -> mlp-GEMM(+res)
// GEMMs: mma.sync.m16n8k8 tf32, cp.async 4-stage pipeline, LDS.128 fragments.
// ---------------------------------------------------------------------------

#define S_LEN 4096
#define B_SZ  4
#define D_DIM 1024
#define H_DIM 4096
#define M_ROWS (B_SZ * S_LEN)      // 16384
#define CH_L  128
#define CH_C  (S_LEN / CH_L)       // 32

// Scratch (device globals: allocation-free per harness rules)
__device__ float g_normed[(size_t)M_ROWS * D_DIM];
__device__ float g_k[(size_t)M_ROWS * D_DIM];
__device__ float g_v[(size_t)M_ROWS * D_DIM];
__device__ float g_r[(size_t)M_ROWS * D_DIM];
__device__ float g_a[(size_t)M_ROWS * D_DIM];
__device__ float g_x1[(size_t)M_ROWS * D_DIM];
__device__ float g_h2[(size_t)M_ROWS * H_DIM];
__device__ float g_carry[CH_C * B_SZ * D_DIM];
__device__ float g_entry[CH_C * B_SZ * D_DIM];
__device__ float g_wcvt[12 * 1024 * 1024];     // tf32-rounded weights

__device__ __forceinline__ uint32_t smem_to_u32(const void* p) {
    uint32_t a;
    asm("{ .reg .u64 t; cvta.to.shared.u64 t, %1; cvt.u32.u64 %0, t; }"
        : "=r"(a) : "l"(p));
    return a;
}

__device__ __forceinline__ uint32_t f2tf32(float f) {
    uint32_t u;
    asm("cvt.rna.tf32.f32 %0, %1;" : "=r"(u) : "f"(f));
    return u;
}
__device__ __forceinline__ float rnd_tf32(float f) {
    return __uint_as_float(f2tf32(f));
}

#define CP_ASYNC16(dst, src) \
    asm volatile("cp.async.cg.shared.global [%0], [%1], 16;" \
                 :: "r"(dst), "l"(src) : "memory")
#define CP_COMMIT() asm volatile("cp.async.commit_group;" ::: "memory")
#define CP_WAIT2()  asm volatile("cp.async.wait_group 2;" ::: "memory")

#define LDS128(r0, r1, r2, r3, addr) \
    asm volatile("ld.shared.v4.b32 {%0,%1,%2,%3}, [%4];" \
                 : "=r"(r0), "=r"(r1), "=r"(r2), "=r"(r3) : "r"(addr))

#define MMA_TF32(d, a0, a1, a2, a3, b0, b1) \
    asm volatile( \
        "mma.sync.aligned.m16n8k8.row.col.f32.tf32.tf32.f32 " \
        "{%0,%1,%2,%3}, {%4,%5,%6,%7}, {%8,%9}, {%0,%1,%2,%3};\n" \
        : "+f"((d)[0]), "+f"((d)[1]), "+f"((d)[2]), "+f"((d)[3]) \
        : "r"(a0), "r"(a1), "r"(a2), "r"(a3), "r"(b0), "r"(b1))

// ---------------------------------------------------------------------------
// Weight pre-round to tf32 (rna), float4 grid-stride
// ---------------------------------------------------------------------------
__global__ void cvt_tf32_kernel(const float* __restrict__ in, float* __restrict__ out, int n4) {
    const int i = blockIdx.x * 256 + threadIdx.x;
    if (i < n4) {
        const float4 v = reinterpret_cast<const float4*>(in)[i];
        float4 o;
        o.x = rnd_tf32(v.x); o.y = rnd_tf32(v.y);
        o.z = rnd_tf32(v.z); o.w = rnd_tf32(v.w);
        reinterpret_cast<float4*>(out)[i] = o;
    }
}

// ---------------------------------------------------------------------------
// RMS norm (output pre-rounded to tf32: it is only ever a GEMM A operand)
// ---------------------------------------------------------------------------
__global__ void rms_kernel(const float* __restrict__ x, float* __restrict__ out) {
    const int row = blockIdx.x;
    const float4 va = reinterpret_cast<const float4*>(x + (size_t)row * D_DIM)[threadIdx.x];
    float ss = va.x * va.x + va.y * va.y + va.z * va.z + va.w * va.w;
    #pragma unroll
    for (int o = 16; o > 0; o >>= 1) ss += __shfl_xor_sync(0xffffffffu, ss, o);

    __shared__ float wsum[8];
    const int wid = threadIdx.x >> 5, lid = threadIdx.x & 31;
    if (lid == 0) wsum[wid] = ss;
    __syncthreads();
    if (wid == 0) {
        float t = (lid < 8) ? wsum[lid] : 0.f;
        #pragma unroll
        for (int o = 4; o > 0; o >>= 1) t += __shfl_xor_sync(0xffffffffu, t, o);
        if (lid == 0) wsum[0] = t;
    }
    __syncthreads();
    const float inv = rsqrtf(wsum[0] * (1.0f / (float)D_DIM) + 1e-6f);
    float4 o4;
    o4.x = rnd_tf32(va.x * inv); o4.y = rnd_tf32(va.y * inv);
    o4.z = rnd_tf32(va.z * inv); o4.w = rnd_tf32(va.w * inv);
    reinterpret_cast<float4*>(out + (size_t)row * D_DIM)[threadIdx.x] = o4;
}

// ---------------------------------------------------------------------------
// RWKV chunked scan (exact factorization, per-channel constant decay)
// ---------------------------------------------------------------------------
__global__ void scan_carry(const float* __restrict__ k, const float* __restrict__ v,
                           const float* __restrict__ td) {
    const int d = blockIdx.x * 256 + threadIdx.x;
    const int c = blockIdx.y, b = blockIdx.z;
    const float ew = expf(-expf(td[d]));
    size_t base = ((size_t)b * S_LEN + (size_t)c * CH_L) * D_DIM + d;
    float carry = 0.f;
    #pragma unroll 4
    for (int i = 0; i < CH_L; i++) {
        const float kv = k[base] * v[base];
        carry = ew * carry + kv;
        base += D_DIM;
    }
    g_carry[((size_t)c * B_SZ + b) * D_DIM + d] = carry;
}

__global__ void scan_combine(const float* __restrict__ td) {
    const int d = blockIdx.x * 256 + threadIdx.x;
    const int b = blockIdx.y;
    const float ewL = expf(-(float)CH_L * expf(td[d]));
    float s = 0.f;
    #pragma unroll
    for (int c = 0; c < CH_C; c++) {
        const size_t idx = ((size_t)c * B_SZ + b) * D_DIM + d;
        g_entry[idx] = s;
        s = ewL * s + g_carry[idx];
    }
}

__global__ void scan_apply(const float* __restrict__ k, const float* __restrict__ v,
                           const float* __restrict__ r,
                           const float* __restrict__ td, const float* __restrict__ tfirst) {
    const int d = blockIdx.x * 256 + threadIdx.x;
    const int c = blockIdx.y, b = blockIdx.z;
    const float ew = expf(-expf(td[d]));
    const float eu = expf(tfirst[d]);
    float s = g_entry[((size_t)c * B_SZ + b) * D_DIM + d];
    size_t base = ((size_t)b * S_LEN + (size_t)c * CH_L) * D_DIM + d;
    #pragma unroll 4
    for (int i = 0; i < CH_L; i++) {
        const float kv = k[base] * v[base];
        const float wkv = s + eu * kv;
        g_a[base] = rnd_tf32(r[base] * wkv);   // GEMM A operand: pre-round
        s = ew * s + kv;
        base += D_DIM;
    }
}

// ---------------------------------------------------------------------------
// tf32 mma.sync GEMM: C[M,N] = A[M,K] @ B[N,K]^T, inputs pre-rounded to tf32.
// Block 128x128x16, 256 threads (8 warps 2x4), warp tile 64x32.
// cp.async 4-stage ring (64KB smem), 2 CTAs/SM.
// K-major smem rows of 64B; LDS.128 fragments via logical-k relabeling.
// EPI: 0=none 1=sigmoid 2=res+scale*acc 3=(leaky0.5)^2 (tf32-rounded store)
// ---------------------------------------------------------------------------
#define NST 4
#define STAGE_BYTES 16384    // A 8KB + B 8KB
#define SMEM_TOTAL (NST * STAGE_BYTES)

template <int EPI>
__global__ void __launch_bounds__(256, 2) gemm_mma(
    const float* __restrict__ A, const float* __restrict__ Bw,
    float* __restrict__ C, int K, int N,
    const float* __restrict__ res, const float* __restrict__ scale)
{
    extern __shared__ char smem[];
    const uint32_t sb = smem_to_u32(smem);
    const int tid = threadIdx.x;
    const int bn = blockIdx.x, bm = blockIdx.y;
    const int warp = tid >> 5, lane = tid & 31;
    const int wm = warp >> 2, wn = warp & 3;      // 2x4 warp grid
    const int gid = lane >> 2, tig = lane & 3;

    const float* Ab = A + (size_t)bm * 128 * K;
    const float* Bb = Bw + (size_t)bn * 128 * K;

    // cp.async source/dest mapping: stage = 512 A-chunks + 512 B-chunks (16B).
    // chunk i -> row i>>2, kchunk i&3 ; smem offset i*16.
    const int i0 = tid, i1 = 256 + tid;
    const float* gA0 = Ab + (size_t)(i0 >> 2) * K + (i0 & 3) * 4;
    const float* gA1 = Ab + (size_t)(i1 >> 2) * K + (i1 & 3) * 4;
    const float* gB0 = Bb + (size_t)(i0 >> 2) * K + (i0 & 3) * 4;
    const float* gB1 = Bb + (size_t)(i1 >> 2) * K + (i1 & 3) * 4;
    const uint32_t dA0 = sb + i0 * 16, dA1 = sb + i1 * 16;
    const uint32_t dB0 = sb + 8192 + i0 * 16, dB1 = sb + 8192 + i1 * 16;

    float acc[4][4][4];
    #pragma unroll
    for (int i = 0; i < 4; i++)
        #pragma unroll
        for (int j = 0; j < 4; j++)
            #pragma unroll
            for (int l = 0; l < 4; l++) acc[i][j][l] = 0.f;

    const int KT = K >> 4;

    // prologue: stages 0..2
    #pragma unroll
    for (int s = 0; s < NST - 1; s++) {
        const uint32_t so = s * STAGE_BYTES;
        const int ko = s * 16;
        CP_ASYNC16(dA0 + so, gA0 + ko);
        CP_ASYNC16(dA1 + so, gA1 + ko);
        CP_ASYNC16(dB0 + so, gB0 + ko);
        CP_ASYNC16(dB1 + so, gB1 + ko);
        CP_COMMIT();
    }

    const uint32_t a_base = sb + (uint32_t)(wm * 64 + gid) * 64 + tig * 16;
    const uint32_t b_base = sb + 8192 + (uint32_t)(wn * 32 + gid) * 64 + tig * 16;

    for (int kt = 0; kt < KT; kt++) {
        CP_WAIT2();
        __syncthreads();

        const uint32_t so = (uint32_t)(kt & (NST - 1)) * STAGE_BYTES;
        uint32_t bf[4][4];
        #pragma unroll
        for (int ni = 0; ni < 4; ni++)
            LDS128(bf[ni][0], bf[ni][1], bf[ni][2], bf[ni][3], b_base + so + ni * 512);

        #pragma unroll
        for (int mi = 0; mi < 4; mi++) {
            uint32_t lo0, lo1, lo2, lo3, hi0, hi1, hi2, hi3;
            LDS128(lo0, lo1, lo2, lo3, a_base + so + mi * 1024);
            LDS128(hi0, hi1, hi2, hi3, a_base + so + mi * 1024 + 512);
            #pragma unroll
            for (int ni = 0; ni < 4; ni++) {
                MMA_TF32(acc[mi][ni], lo0, hi0, lo1, hi1, bf[ni][0], bf[ni][1]);
                MMA_TF32(acc[mi][ni], lo2, hi2, lo3, hi3, bf[ni][2], bf[ni][3]);
            }
        }

        const int kn = kt + NST - 1;
        if (kn < KT) {
            const uint32_t sn = (uint32_t)(kn & (NST - 1)) * STAGE_BYTES;
            const int ko = kn * 16;
            CP_ASYNC16(dA0 + sn, gA0 + ko);
            CP_ASYNC16(dA1 + sn, gA1 + ko);
            CP_ASYNC16(dB0 + sn, gB0 + ko);
            CP_ASYNC16(dB1 + sn, gB1 + ko);
        }
        CP_COMMIT();
    }

    // epilogue (C fragment: c0,c1 @ row gid cols 2tig,2tig+1; c2,c3 @ row gid+8)
    const int row0 = bm * 128 + wm * 64 + gid;
    const int col0 = bn * 128 + wn * 32 + 2 * tig;
    #pragma unroll
    for (int mi = 0; mi < 4; mi++) {
        #pragma unroll
        for (int ni = 0; ni < 4; ni++) {
            const int gc = col0 + ni * 8;
            #pragma unroll
            for (int h = 0; h < 2; h++) {
                const int gr = row0 + mi * 16 + h * 8;
                float v0 = acc[mi][ni][2 * h + 0];
                float v1 = acc[mi][ni][2 * h + 1];
                if (EPI == 1) {
                    v0 = 1.f / (1.f + expf(-v0));
                    v1 = 1.f / (1.f + expf(-v1));
                } else if (EPI == 2) {
                    const float2 rr = *reinterpret_cast<const float2*>(res + (size_t)gr * N + gc);
                    const float2 sc = *reinterpret_cast<const float2*>(scale + gc);
                    v0 = rr.x + sc.x * v0;
                    v1 = rr.y + sc.y * v1;
                } else if (EPI == 3) {
                    const float t0 = v0 > 0.f ? v0 : 0.5f * v0;
                    const float t1 = v1 > 0.f ? v1 : 0.5f * v1;
                    v0 = rnd_tf32(t0 * t0);    // next GEMM's A operand
                    v1 = rnd_tf32(t1 * t1);
                }
                *reinterpret_cast<float2*>(C + (size_t)gr * N + gc) = make_float2(v0, v1);
            }
        }
    }
}

// ---------------------------------------------------------------------------
// Launch
// ---------------------------------------------------------------------------
extern "C" void kernel_launch(void* const* d_in, const int* in_sizes, int n_in,
                              void* d_out, int out_size) {
    const float* x     = (const float*)d_in[0];
    const float* Wk    = (const float*)d_in[1];
    const float* Wv    = (const float*)d_in[2];
    const float* Wr    = (const float*)d_in[3];
    const float* Wo    = (const float*)d_in[4];
    const float* td    = (const float*)d_in[5];
    const float* tfst  = (const float*)d_in[6];
    const float* mscl  = (const float*)d_in[7];
    const float* Wfc   = (const float*)d_in[8];
    const float* Wmlp  = (const float*)d_in[9];
    const float* pscl  = (const float*)d_in[10];
    float* out = (float*)d_out;

    float *p_normed, *p_k, *p_v, *p_r, *p_a, *p_x1, *p_h2, *p_w;
    cudaGetSymbolAddress((void**)&p_normed, g_normed);
    cudaGetSymbolAddress((void**)&p_k, g_k);
    cudaGetSymbolAddress((void**)&p_v, g_v);
    cudaGetSymbolAddress((void**)&p_r, g_r);
    cudaGetSymbolAddress((void**)&p_a, g_a);
    cudaGetSymbolAddress((void**)&p_x1, g_x1);
    cudaGetSymbolAddress((void**)&p_h2, g_h2);
    cudaGetSymbolAddress((void**)&p_w, g_wcvt);

    float* cWk   = p_w;
    float* cWv   = p_w + (size_t)1 * 1024 * 1024;
    float* cWr   = p_w + (size_t)2 * 1024 * 1024;
    float* cWo   = p_w + (size_t)3 * 1024 * 1024;
    float* cWfc  = p_w + (size_t)4 * 1024 * 1024;
    float* cWmlp = p_w + (size_t)8 * 1024 * 1024;

    cudaFuncSetAttribute(gemm_mma<0>, cudaFuncAttributeMaxDynamicSharedMemorySize, SMEM_TOTAL);
    cudaFuncSetAttribute(gemm_mma<1>, cudaFuncAttributeMaxDynamicSharedMemorySize, SMEM_TOTAL);
    cudaFuncSetAttribute(gemm_mma<2>, cudaFuncAttributeMaxDynamicSharedMemorySize, SMEM_TOTAL);
    cudaFuncSetAttribute(gemm_mma<3>, cudaFuncAttributeMaxDynamicSharedMemorySize, SMEM_TOTAL);

    const dim3 gemmD(D_DIM / 128, M_ROWS / 128);   // (8, 128)
    const dim3 gemmH(H_DIM / 128, M_ROWS / 128);   // (32, 128)
    const int n1M4 = (1024 * 1024) / 4, n4M4 = (4 * 1024 * 1024) / 4;

    // 0) pre-round weights to tf32
    cvt_tf32_kernel<<<(n1M4 + 255) / 256, 256>>>(Wk, cWk, n1M4);
    cvt_tf32_kernel<<<(n1M4 + 255) / 256, 256>>>(Wv, cWv, n1M4);
    cvt_tf32_kernel<<<(n1M4 + 255) / 256, 256>>>(Wr, cWr, n1M4);
    cvt_tf32_kernel<<<(n1M4 + 255) / 256, 256>>>(Wo, cWo, n1M4);
    cvt_tf32_kernel<<<(n4M4 + 255) / 256, 256>>>(Wfc, cWfc, n4M4);
    cvt_tf32_kernel<<<(n4M4 + 255) / 256, 256>>>(Wmlp, cWmlp, n4M4);

    // 1) RMS(x)
    rms_kernel<<<M_ROWS, 256>>>(x, p_normed);
    // 2) k, v, r
    gemm_mma<0><<<gemmD, 256, SMEM_TOTAL>>>(p_normed, cWk, p_k, D_DIM, D_DIM, nullptr, nullptr);
    gemm_mma<0><<<gemmD, 256, SMEM_TOTAL>>>(p_normed, cWv, p_v, D_DIM, D_DIM, nullptr, nullptr);
    gemm_mma<1><<<gemmD, 256, SMEM_TOTAL>>>(p_normed, cWr, p_r, D_DIM, D_DIM, nullptr, nullptr);
    // 3) chunked RWKV scan, fuse r*wkv into g_a
    scan_carry<<<dim3(D_DIM / 256, CH_C, B_SZ), 256>>>(p_k, p_v, td);
    scan_combine<<<dim3(D_DIM / 256, B_SZ), 256>>>(td);
    scan_apply<<<dim3(D_DIM / 256, CH_C, B_SZ), 256>>>(p_k, p_v, p_r, td, tfst);
    // 4) o-GEMM + residual -> x1
    gemm_mma<2><<<gemmD, 256, SMEM_TOTAL>>>(p_a, cWo, p_x1, D_DIM, D_DIM, x, mscl);
    // 5) RMS(x1)
    rms_kernel<<<M_ROWS, 256>>>(p_x1, p_normed);
    // 6) fc-GEMM with leaky(0.5)^2 epilogue -> h2
    gemm_mma<3><<<gemmH, 256, SMEM_TOTAL>>>(p_normed, cWfc, p_h2, D_DIM, H_DIM, nullptr, nullptr);
    // 7) mlp-GEMM + residual -> out
    gemm_mma<2><<<gemmD, 256, SMEM_TOTAL>>>(p_h2, cWmlp, out, H_DIM, D_DIM, p_x1, pscl);
}